// round 6
// baseline (speedup 1.0000x reference)
#include <cuda_runtime.h>

#define TT 300
// SLAYER constants
#define D_SR 0.9048374180359595f    // exp(-Ts/tauSr), tauSr=10
#define B_SR 0.2718281828459045f    // e*Ts/tauSr
#define D_RF 0.3678794411714423f    // exp(-Ts/tauRef), tauRef=1
#define A_RF -54.365636569180902f   // -scaleRef*theta*e*Ts/tauRef
#define THETA 10.0f
#define PGAIN 11.0f                 // 1.1*theta

// ---- scratch arenas (time-major [t][n][c][h][w]) ----
// A: v1[300x100352] / v3[300x50176] / psp5[300x25088]
// C: psp2[300x25088]  / v5[300x25088]
// D: psp0[300x7200] / psp4[300x12544]
__device__ float g_bufA[30105600];
__device__ float g_bufC[7526400];
__device__ float g_bufD[3763200];
__device__ float g_bufY[24000];

// --- packed f32x2 helpers (sm_100+). Each half is an exact fmaf. ---
__device__ __forceinline__ unsigned long long pk2(float lo, float hi) {
    unsigned long long d;
    asm("mov.b64 %0, {%1, %2};" : "=l"(d)
        : "r"(__float_as_uint(lo)), "r"(__float_as_uint(hi)));
    return d;
}
__device__ __forceinline__ void fma2(unsigned long long& d, unsigned long long a,
                                     unsigned long long b) {
    asm("fma.rn.f32x2 %0, %1, %2, %0;" : "+l"(d) : "l"(a), "l"(b));
}
__device__ __forceinline__ void upk2(unsigned long long d, float& lo, float& hi) {
    unsigned int l, h;
    asm("mov.b64 {%0, %1}, %2;" : "=r"(l), "=r"(h) : "l"(d));
    lo = __uint_as_float(l);
    hi = __uint_as_float(h);
}

// --- exact-order recurrence steps (no fma contraction, matching XLA) ---
__device__ __forceinline__ float psp_step(float x, float& p, float& q) {
    q = __fmul_rn(D_SR, __fadd_rn(q, p));
    float out = __fmul_rn(B_SR, q);
    p = __fadd_rn(__fmul_rn(D_SR, p), x);
    return out;
}
__device__ __forceinline__ float spike_step(float u, float& p, float& q) {
    q = __fmul_rn(D_RF, __fadd_rn(q, p));
    float m = __fadd_rn(u, __fmul_rn(A_RF, q));
    float s = (m >= THETA) ? 1.0f : 0.0f;
    p = __fadd_rn(__fmul_rn(D_RF, p), s);
    return s;
}

// K0: psp of raw input. in [j=7200][t] -> time-major psp0 in bufD.
__global__ void k_psp0(const float* __restrict__ in) {
    int j = blockIdx.x * blockDim.x + threadIdx.x;
    if (j >= 7200) return;
    const float4* xp = reinterpret_cast<const float4*>(in + (size_t)j * TT);
    float p = 0.f, q = 0.f;
    float4 cur = xp[0];
    for (int tb = 0; tb < 75; tb++) {
        float4 nxt;
        if (tb < 74) nxt = xp[tb + 1];
        g_bufD[(size_t)(4 * tb + 0) * 7200 + j] = psp_step(cur.x, p, q);
        g_bufD[(size_t)(4 * tb + 1) * 7200 + j] = psp_step(cur.y, p, q);
        g_bufD[(size_t)(4 * tb + 2) * 7200 + j] = psp_step(cur.z, p, q);
        g_bufD[(size_t)(4 * tb + 3) * 7200 + j] = psp_step(cur.w, p, q);
        cur = nxt;
    }
}

// Fused: 4 parent drives -> [spike->psp]x4 -> pool*gain -> spike -> psp.
__global__ void k_fused_pool(const float* __restrict__ v, float* __restrict__ po,
                             int C, int Ho, int Wo, int nn_in, int nn_out) {
    int i = blockIdx.x * blockDim.x + threadIdx.x;
    if (i >= nn_out) return;
    int per = C * Ho * Wo;
    int n = i / per;
    int rem = i - n * per;
    int c = rem / (Ho * Wo);
    int r2 = rem - c * (Ho * Wo);
    int oh = r2 / Wo, ow = r2 - oh * Wo;
    int Wi = 2 * Wo;
    size_t base = ((size_t)(n * C + c) * (2 * Ho) + 2 * oh) * Wi + 2 * ow;

    float ps[4], qs[4], pp[4], qq[4];
#pragma unroll
    for (int jj = 0; jj < 4; jj++) { ps[jj] = 0.f; qs[jj] = 0.f; pp[jj] = 0.f; qq[jj] = 0.f; }
    float psO = 0.f, qsO = 0.f, ppO = 0.f, qqO = 0.f;

    const int CH = 10;
    float cur[4 * CH], nxt[4 * CH];
#pragma unroll
    for (int k = 0; k < CH; k++) {
        const float* bp = v + (size_t)k * nn_in + base;
        cur[4 * k + 0] = bp[0];
        cur[4 * k + 1] = bp[1];
        cur[4 * k + 2] = bp[Wi];
        cur[4 * k + 3] = bp[Wi + 1];
    }
    for (int tb = 0; tb < TT / CH; tb++) {
        if (tb + 1 < TT / CH) {
#pragma unroll
            for (int k = 0; k < CH; k++) {
                const float* bp = v + (size_t)((tb + 1) * CH + k) * nn_in + base;
                nxt[4 * k + 0] = bp[0];
                nxt[4 * k + 1] = bp[1];
                nxt[4 * k + 2] = bp[Wi];
                nxt[4 * k + 3] = bp[Wi + 1];
            }
        }
#pragma unroll
        for (int k = 0; k < CH; k++) {
            float pv[4];
#pragma unroll
            for (int jj = 0; jj < 4; jj++) {
                float s = spike_step(cur[4 * k + jj], ps[jj], qs[jj]);
                pv[jj] = psp_step(s, pp[jj], qq[jj]);
            }
            float u = __fmul_rn(PGAIN,
                __fadd_rn(__fadd_rn(pv[0], pv[1]), __fadd_rn(pv[2], pv[3])));
            float s2 = spike_step(u, psO, qsO);
            po[(size_t)(tb * CH + k) * nn_out + i] = psp_step(s2, ppO, qqO);
        }
#pragma unroll
        for (int k = 0; k < 4 * CH; k++) cur[k] = nxt[k];
    }
}

// Fused spike(v) -> psp(s), chunked double-buffer prefetch.
__global__ void k_spike_psp(const float* __restrict__ v, float* __restrict__ po, int nn) {
    int i = blockIdx.x * blockDim.x + threadIdx.x;
    if (i >= nn) return;
    float ps = 0.f, qs = 0.f, pp = 0.f, qq = 0.f;
    const int CH = 10;
    float cur[CH], nxt[CH];
#pragma unroll
    for (int k = 0; k < CH; k++) cur[k] = v[(size_t)k * nn + i];
    for (int tb = 0; tb < TT / CH; tb++) {
        if (tb + 1 < TT / CH) {
#pragma unroll
            for (int k = 0; k < CH; k++)
                nxt[k] = v[(size_t)((tb + 1) * CH + k) * nn + i];
        }
#pragma unroll
        for (int k = 0; k < CH; k++) {
            float s = spike_step(cur[k], ps, qs);
            po[(size_t)(tb * CH + k) * nn + i] = psp_step(s, pp, qq);
        }
#pragma unroll
        for (int k = 0; k < CH; k++) cur[k] = nxt[k];
    }
}

// K1: conv1 (1->16, 5x5, pad1, 30->28). D -> A. float2 row loads.
__global__ void __launch_bounds__(448) k_conv1(const float* __restrict__ w) {
    __shared__ float xs[900];
    __shared__ float ws[400];
    int b = blockIdx.x;
    int t = b >> 3;
    int n = b & 7;
    const float* xp = g_bufD + (size_t)t * 7200 + n * 900;
    for (int i = threadIdx.x; i < 900; i += 448) xs[i] = xp[i];
    for (int i = threadIdx.x; i < 400; i += 448) ws[i] = w[i];
    __syncthreads();
    int o = threadIdx.x / 28;
    int oh = threadIdx.x % 28;
    float acc[28];
#pragma unroll
    for (int p = 0; p < 28; p++) acc[p] = 0.f;
#pragma unroll
    for (int kh = 0; kh < 5; kh++) {
        int ih = oh - 1 + kh;
        if ((unsigned)ih < 30u) {
            float r[32];
            r[0] = 0.f; r[31] = 0.f;
#pragma unroll
            for (int jj = 0; jj < 15; jj++) {  // ih*30 even -> 8B aligned
                float2 v2 = *reinterpret_cast<const float2*>(&xs[ih * 30 + 2 * jj]);
                r[1 + 2 * jj] = v2.x;
                r[2 + 2 * jj] = v2.y;
            }
#pragma unroll
            for (int kw = 0; kw < 5; kw++) {
                float wv = ws[o * 25 + kh * 5 + kw];
#pragma unroll
                for (int p = 0; p < 28; p++) acc[p] = fmaf(wv, r[p + kw], acc[p]);
            }
        }
    }
    float* vp = g_bufA + (size_t)t * 100352 + ((n * 16 + o) * 28 + oh) * 28;
#pragma unroll
    for (int p = 0; p < 28; p++) vp[p] = acc[p];
}

// K2: conv2 (16->32, 3x3, pad1, 14x14): C(psp2) -> A(v3).
// 224 threads = (o:16, oh:14); each thread computes channels o and o+16.
// Packed f32x2 FMA: accumulators are 7 pairs per channel; per-output
// accumulation order (c asc, kh asc, kw asc) identical to scalar version.
__global__ void __launch_bounds__(224) k_conv2(const float* __restrict__ w) {
    __shared__ float xs[3136];   // 16*14*14
    __shared__ float ws[4608];   // 32*16*9
    int b = blockIdx.x;
    int t = b >> 3;
    int n = b & 7;
    const float* xp = g_bufC + (size_t)t * 25088 + n * 3136;
    for (int i = threadIdx.x; i < 3136; i += 224) xs[i] = xp[i];
    for (int i = threadIdx.x; i < 4608; i += 224) ws[i] = w[i];
    __syncthreads();
    int o = threadIdx.x / 14, oh = threadIdx.x % 14;
    unsigned long long a0[7], a1[7];
    const unsigned long long Z = pk2(0.f, 0.f);
#pragma unroll
    for (int i = 0; i < 7; i++) { a0[i] = Z; a1[i] = Z; }
    for (int c = 0; c < 16; c++) {
#pragma unroll
        for (int kh = 0; kh < 3; kh++) {
            int ih = oh - 1 + kh;
            float r[16];
            r[0] = 0.f; r[15] = 0.f;
            if ((unsigned)ih < 14u) {
#pragma unroll
                for (int jj = 0; jj < 7; jj++) {  // c*196+ih*14 even -> aligned
                    float2 v2 = *reinterpret_cast<const float2*>(&xs[c * 196 + ih * 14 + 2 * jj]);
                    r[1 + 2 * jj] = v2.x;
                    r[2 + 2 * jj] = v2.y;
                }
            } else {
#pragma unroll
                for (int j = 0; j < 14; j++) r[j + 1] = 0.f;
            }
#pragma unroll
            for (int kw = 0; kw < 3; kw++) {
                float w0 = ws[((o * 16 + c) * 3 + kh) * 3 + kw];
                float w1 = ws[(((o + 16) * 16 + c) * 3 + kh) * 3 + kw];
                unsigned long long w0d = pk2(w0, w0);
                unsigned long long w1d = pk2(w1, w1);
#pragma unroll
                for (int i = 0; i < 7; i++) {
                    unsigned long long xv = pk2(r[2 * i + kw], r[2 * i + 1 + kw]);
                    fma2(a0[i], w0d, xv);
                    fma2(a1[i], w1d, xv);
                }
            }
        }
    }
    float* vp0 = g_bufA + (size_t)t * 50176 + ((n * 32 + o) * 14 + oh) * 14;
    float* vp1 = g_bufA + (size_t)t * 50176 + ((n * 32 + o + 16) * 14 + oh) * 14;
#pragma unroll
    for (int i = 0; i < 7; i++) {
        float lo, hi;
        upk2(a0[i], lo, hi);
        vp0[2 * i] = lo; vp0[2 * i + 1] = hi;
        upk2(a1[i], lo, hi);
        vp1[2 * i] = lo; vp1[2 * i + 1] = hi;
    }
}

// K3: conv3 (32->64, 3x3, pad1, 7x7): D(psp4) -> C(v5).
// Block handles 2 (t,n) units (weights smem amortized). 224 threads:
// g = tid/112 selects the unit; within: (o:16, oh:7), 4 channels per thread
// (o, o+16, o+32, o+48). x rows padded to stride 8 for float2 loads.
// Packed f32x2 FMA (3 pairs + 1 scalar per channel), exact order preserved.
extern __shared__ float dynsm[];
__global__ void __launch_bounds__(224) k_conv3(const float* __restrict__ w) {
    float* ws = dynsm;            // 18432 floats
    float* xsp = dynsm + 18432;   // 2 * 1792 floats (rows padded to 8)
    int b = blockIdx.x;
    int u0 = 2 * b;
    for (int i = threadIdx.x; i < 18432; i += 224) ws[i] = w[i];
    for (int i = threadIdx.x; i < 3136; i += 224) {
        int g2 = i / 1568;
        int rem = i - g2 * 1568;
        int c = rem / 49;
        int rr = rem - c * 49;
        int ih = rr / 7;
        int j = rr - ih * 7;
        int u = u0 + g2;
        const float* xp = g_bufD + (size_t)(u >> 3) * 12544 + (u & 7) * 1568;
        xsp[g2 * 1792 + c * 56 + ih * 8 + j] = xp[rem];
    }
    __syncthreads();
    int g = threadIdx.x / 112;
    int idx = threadIdx.x - g * 112;
    int o = idx / 7, oh = idx % 7;
    const float* X = xsp + g * 1792;
    int u = u0 + g;
    int t = u >> 3, n = u & 7;

    unsigned long long aP[4][3];
    float aS[4];
    const unsigned long long Z = pk2(0.f, 0.f);
#pragma unroll
    for (int oo = 0; oo < 4; oo++) {
        aP[oo][0] = Z; aP[oo][1] = Z; aP[oo][2] = Z; aS[oo] = 0.f;
    }
    for (int c = 0; c < 32; c++) {
#pragma unroll
        for (int kh = 0; kh < 3; kh++) {
            int ih = oh - 1 + kh;
            float r[9];
            r[0] = 0.f; r[8] = 0.f;
            if ((unsigned)ih < 7u) {
                int base = c * 56 + ih * 8;  // even -> 8B aligned
                float2 v0 = *reinterpret_cast<const float2*>(&X[base]);
                float2 v1 = *reinterpret_cast<const float2*>(&X[base + 2]);
                float2 v2 = *reinterpret_cast<const float2*>(&X[base + 4]);
                r[1] = v0.x; r[2] = v0.y;
                r[3] = v1.x; r[4] = v1.y;
                r[5] = v2.x; r[6] = v2.y;
                r[7] = X[base + 6];
            } else {
#pragma unroll
                for (int j = 1; j < 8; j++) r[j] = 0.f;
            }
#pragma unroll
            for (int kw = 0; kw < 3; kw++) {
                unsigned long long x0 = pk2(r[kw], r[kw + 1]);
                unsigned long long x1 = pk2(r[kw + 2], r[kw + 3]);
                unsigned long long x2 = pk2(r[kw + 4], r[kw + 5]);
                float xsc = r[kw + 6];
#pragma unroll
                for (int oo = 0; oo < 4; oo++) {
                    float wv = ws[(((o + oo * 16) * 32 + c) * 3 + kh) * 3 + kw];
                    unsigned long long wd = pk2(wv, wv);
                    fma2(aP[oo][0], wd, x0);
                    fma2(aP[oo][1], wd, x1);
                    fma2(aP[oo][2], wd, x2);
                    aS[oo] = fmaf(wv, xsc, aS[oo]);
                }
            }
        }
    }
#pragma unroll
    for (int oo = 0; oo < 4; oo++) {
        float* vp = g_bufC + (size_t)t * 25088 + ((n * 64 + o + oo * 16) * 7 + oh) * 7;
        float lo, hi;
        upk2(aP[oo][0], lo, hi); vp[0] = lo; vp[1] = hi;
        upk2(aP[oo][1], lo, hi); vp[2] = lo; vp[3] = hi;
        upk2(aP[oo][2], lo, hi); vp[4] = lo; vp[5] = hi;
        vp[6] = aS[oo];
    }
}

// K4: dense head, 4 timesteps per block (weight traffic /4): A -> Y.
// j-stripe and tree reduction identical to previous version per (t,o).
__global__ void __launch_bounds__(256) k_fc(const float* __restrict__ w) {
    __shared__ float red[256];
    int b = blockIdx.x;
    int n = b & 7;
    int t0 = (b >> 3) * 4;
    const float* xp0 = g_bufA + (size_t)(t0 + 0) * 25088 + n * 3136;
    const float* xp1 = g_bufA + (size_t)(t0 + 1) * 25088 + n * 3136;
    const float* xp2 = g_bufA + (size_t)(t0 + 2) * 25088 + n * 3136;
    const float* xp3 = g_bufA + (size_t)(t0 + 3) * 25088 + n * 3136;
    float acc[40];
#pragma unroll
    for (int i = 0; i < 40; i++) acc[i] = 0.f;
    for (int j = threadIdx.x; j < 3136; j += 256) {
        float x0 = xp0[j], x1 = xp1[j], x2 = xp2[j], x3 = xp3[j];
#pragma unroll
        for (int o = 0; o < 10; o++) {
            float wv = w[o * 3136 + j];
            acc[0 * 10 + o] = fmaf(x0, wv, acc[0 * 10 + o]);
            acc[1 * 10 + o] = fmaf(x1, wv, acc[1 * 10 + o]);
            acc[2 * 10 + o] = fmaf(x2, wv, acc[2 * 10 + o]);
            acc[3 * 10 + o] = fmaf(x3, wv, acc[3 * 10 + o]);
        }
    }
    for (int tt = 0; tt < 4; tt++) {
#pragma unroll
        for (int o = 0; o < 10; o++) {
            red[threadIdx.x] = acc[tt * 10 + o];
            __syncthreads();
            for (int st = 128; st > 0; st >>= 1) {
                if (threadIdx.x < st) red[threadIdx.x] += red[threadIdx.x + st];
                __syncthreads();
            }
            if (threadIdx.x == 0)
                g_bufY[(size_t)(t0 + tt) * 80 + n * 10 + o] = red[0];
            __syncthreads();
        }
    }
}

// K5: final spike scan over 80 output neurons -> [8,10,300]
__global__ void k_spike_out(float* __restrict__ out) {
    int i = threadIdx.x;
    if (i >= 80) return;
    float ps = 0.f, qs = 0.f;
    for (int t = 0; t < TT; t++) {
        out[i * 300 + t] = spike_step(g_bufY[t * 80 + i], ps, qs);
    }
}

extern "C" void kernel_launch(void* const* d_in, const int* in_sizes, int n_in,
                              void* d_out, int out_size) {
    const float* x  = (const float*)d_in[0];   // [8,1,30,30,300]
    const float* w1 = (const float*)d_in[1];   // [16,1,5,5]
    const float* w2 = (const float*)d_in[2];   // [32,16,3,3]
    const float* w3 = (const float*)d_in[3];   // [64,32,3,3]
    const float* wf = (const float*)d_in[4];   // [10,64,7,7]
    float* out = (float*)d_out;

    float *bufA, *bufC, *bufD;
    cudaGetSymbolAddress((void**)&bufA, g_bufA);
    cudaGetSymbolAddress((void**)&bufC, g_bufC);
    cudaGetSymbolAddress((void**)&bufD, g_bufD);

    cudaFuncSetAttribute(k_conv3, cudaFuncAttributeMaxDynamicSharedMemorySize, 88064);

    k_psp0<<<(7200 + 127) / 128, 128>>>(x);                          // x -> D (psp0)
    k_conv1<<<2400, 448>>>(w1);                                      // D -> A (v1)
    k_fused_pool<<<(25088 + 127) / 128, 128>>>(bufA, bufC,
                                   16, 14, 14, 100352, 25088);       // A -> C (psp2)
    k_conv2<<<2400, 224>>>(w2);                                      // C -> A (v3)
    k_fused_pool<<<(12544 + 63) / 64, 64>>>(bufA, bufD,
                                   32, 7, 7, 50176, 12544);          // A -> D (psp4)
    k_conv3<<<1200, 224, 88064>>>(w3);                               // D -> C (v5)
    k_spike_psp<<<(25088 + 127) / 128, 128>>>(bufC, bufA, 25088);    // C -> A (psp5)
    k_fc<<<600, 256>>>(wf);                                          // A -> Y
    k_spike_out<<<1, 128>>>(out);                                    // Y -> out
}

// round 7
// speedup vs baseline: 1.4508x; 1.4508x over previous
#include <cuda_runtime.h>

#define TT 300
// SLAYER constants
#define D_SR 0.9048374180359595f    // exp(-Ts/tauSr), tauSr=10
#define B_SR 0.2718281828459045f    // e*Ts/tauSr
#define D_RF 0.3678794411714423f    // exp(-Ts/tauRef), tauRef=1
#define A_RF -54.365636569180902f   // -scaleRef*theta*e*Ts/tauRef
#define THETA 10.0f
#define PGAIN 11.0f                 // 1.1*theta

// ---- scratch arenas (time-major [t][n][c][h][w]) ----
// A: v1[300x100352] / v3[300x50176] / psp5[300x25088]
// C: psp2[300x25088]  / v5[300x25088]
// D: psp0[300x7200] / psp4[300x12544]
__device__ float g_bufA[30105600];
__device__ float g_bufC[7526400];
__device__ float g_bufD[3763200];
__device__ float g_bufY[24000];

// --- exact-order recurrence steps (no fma contraction, matching XLA) ---
__device__ __forceinline__ float psp_step(float x, float& p, float& q) {
    q = __fmul_rn(D_SR, __fadd_rn(q, p));
    float out = __fmul_rn(B_SR, q);
    p = __fadd_rn(__fmul_rn(D_SR, p), x);
    return out;
}
__device__ __forceinline__ float spike_step(float u, float& p, float& q) {
    q = __fmul_rn(D_RF, __fadd_rn(q, p));
    float m = __fadd_rn(u, __fmul_rn(A_RF, q));
    float s = (m >= THETA) ? 1.0f : 0.0f;
    p = __fadd_rn(__fmul_rn(D_RF, p), s);
    return s;
}

// K0: psp of raw input. in [j=7200][t] -> time-major psp0 in bufD.
__global__ void k_psp0(const float* __restrict__ in) {
    int j = blockIdx.x * blockDim.x + threadIdx.x;
    if (j >= 7200) return;
    const float4* xp = reinterpret_cast<const float4*>(in + (size_t)j * TT);
    float p = 0.f, q = 0.f;
    float4 cur = xp[0];
    for (int tb = 0; tb < 75; tb++) {
        float4 nxt;
        if (tb < 74) nxt = xp[tb + 1];
        g_bufD[(size_t)(4 * tb + 0) * 7200 + j] = psp_step(cur.x, p, q);
        g_bufD[(size_t)(4 * tb + 1) * 7200 + j] = psp_step(cur.y, p, q);
        g_bufD[(size_t)(4 * tb + 2) * 7200 + j] = psp_step(cur.z, p, q);
        g_bufD[(size_t)(4 * tb + 3) * 7200 + j] = psp_step(cur.w, p, q);
        cur = nxt;
    }
}

// Fused: 4 parent drives -> [spike->psp]x4 -> pool*gain -> spike -> psp.
__global__ void k_fused_pool(const float* __restrict__ v, float* __restrict__ po,
                             int C, int Ho, int Wo, int nn_in, int nn_out) {
    int i = blockIdx.x * blockDim.x + threadIdx.x;
    if (i >= nn_out) return;
    int per = C * Ho * Wo;
    int n = i / per;
    int rem = i - n * per;
    int c = rem / (Ho * Wo);
    int r2 = rem - c * (Ho * Wo);
    int oh = r2 / Wo, ow = r2 - oh * Wo;
    int Wi = 2 * Wo;
    size_t base = ((size_t)(n * C + c) * (2 * Ho) + 2 * oh) * Wi + 2 * ow;

    float ps[4], qs[4], pp[4], qq[4];
#pragma unroll
    for (int jj = 0; jj < 4; jj++) { ps[jj] = 0.f; qs[jj] = 0.f; pp[jj] = 0.f; qq[jj] = 0.f; }
    float psO = 0.f, qsO = 0.f, ppO = 0.f, qqO = 0.f;

    const int CH = 10;
    float cur[4 * CH], nxt[4 * CH];
#pragma unroll
    for (int k = 0; k < CH; k++) {
        const float* bp = v + (size_t)k * nn_in + base;
        cur[4 * k + 0] = bp[0];
        cur[4 * k + 1] = bp[1];
        cur[4 * k + 2] = bp[Wi];
        cur[4 * k + 3] = bp[Wi + 1];
    }
    for (int tb = 0; tb < TT / CH; tb++) {
        if (tb + 1 < TT / CH) {
#pragma unroll
            for (int k = 0; k < CH; k++) {
                const float* bp = v + (size_t)((tb + 1) * CH + k) * nn_in + base;
                nxt[4 * k + 0] = bp[0];
                nxt[4 * k + 1] = bp[1];
                nxt[4 * k + 2] = bp[Wi];
                nxt[4 * k + 3] = bp[Wi + 1];
            }
        }
#pragma unroll
        for (int k = 0; k < CH; k++) {
            float pv[4];
#pragma unroll
            for (int jj = 0; jj < 4; jj++) {
                float s = spike_step(cur[4 * k + jj], ps[jj], qs[jj]);
                pv[jj] = psp_step(s, pp[jj], qq[jj]);
            }
            float u = __fmul_rn(PGAIN,
                __fadd_rn(__fadd_rn(pv[0], pv[1]), __fadd_rn(pv[2], pv[3])));
            float s2 = spike_step(u, psO, qsO);
            po[(size_t)(tb * CH + k) * nn_out + i] = psp_step(s2, ppO, qqO);
        }
#pragma unroll
        for (int k = 0; k < 4 * CH; k++) cur[k] = nxt[k];
    }
}

// Fused spike(v) -> psp(s), chunked double-buffer prefetch.
__global__ void k_spike_psp(const float* __restrict__ v, float* __restrict__ po, int nn) {
    int i = blockIdx.x * blockDim.x + threadIdx.x;
    if (i >= nn) return;
    float ps = 0.f, qs = 0.f, pp = 0.f, qq = 0.f;
    const int CH = 10;
    float cur[CH], nxt[CH];
#pragma unroll
    for (int k = 0; k < CH; k++) cur[k] = v[(size_t)k * nn + i];
    for (int tb = 0; tb < TT / CH; tb++) {
        if (tb + 1 < TT / CH) {
#pragma unroll
            for (int k = 0; k < CH; k++)
                nxt[k] = v[(size_t)((tb + 1) * CH + k) * nn + i];
        }
#pragma unroll
        for (int k = 0; k < CH; k++) {
            float s = spike_step(cur[k], ps, qs);
            po[(size_t)(tb * CH + k) * nn + i] = psp_step(s, pp, qq);
        }
#pragma unroll
        for (int k = 0; k < CH; k++) cur[k] = nxt[k];
    }
}

// K1: conv1 (1->16, 5x5, pad1, 30->28). D -> A. 448 thr, float2 row loads.
__global__ void __launch_bounds__(448) k_conv1(const float* __restrict__ w) {
    __shared__ __align__(16) float xs[900];
    __shared__ float ws[400];
    int b = blockIdx.x;
    int t = b >> 3;
    int n = b & 7;
    const float* xp = g_bufD + (size_t)t * 7200 + n * 900;
    for (int i = threadIdx.x; i < 900; i += 448) xs[i] = xp[i];
    for (int i = threadIdx.x; i < 400; i += 448) ws[i] = w[i];
    __syncthreads();
    int o = threadIdx.x / 28;
    int oh = threadIdx.x % 28;
    float acc[28];
#pragma unroll
    for (int p = 0; p < 28; p++) acc[p] = 0.f;
#pragma unroll
    for (int kh = 0; kh < 5; kh++) {
        int ih = oh - 1 + kh;
        if ((unsigned)ih < 30u) {
            float r[32];
            r[0] = 0.f; r[31] = 0.f;
#pragma unroll
            for (int jj = 0; jj < 15; jj++) {  // ih*30 even -> 8B aligned
                float2 v2 = *reinterpret_cast<const float2*>(&xs[ih * 30 + 2 * jj]);
                r[1 + 2 * jj] = v2.x;
                r[2 + 2 * jj] = v2.y;
            }
#pragma unroll
            for (int kw = 0; kw < 5; kw++) {
                float wv = ws[o * 25 + kh * 5 + kw];
#pragma unroll
                for (int p = 0; p < 28; p++) acc[p] = fmaf(wv, r[p + kw], acc[p]);
            }
        }
    }
    float* vp = g_bufA + (size_t)t * 100352 + ((n * 16 + o) * 28 + oh) * 28;
#pragma unroll
    for (int p = 0; p < 28; p++) vp[p] = acc[p];
}

// K2: conv2 (16->32, 3x3, pad1, 14x14): C(psp2) -> A(v3).
// 448 threads = (o:32, oh:14), scalar FFMA, float2 smem row loads.
__global__ void __launch_bounds__(448) k_conv2(const float* __restrict__ w) {
    __shared__ __align__(16) float xs[3136];   // 16*14*14
    __shared__ float ws[4608];                 // 32*16*9
    int b = blockIdx.x;
    int t = b >> 3;
    int n = b & 7;
    const float* xp = g_bufC + (size_t)t * 25088 + n * 3136;
    for (int i = threadIdx.x; i < 3136; i += 448) xs[i] = xp[i];
    for (int i = threadIdx.x; i < 4608; i += 448) ws[i] = w[i];
    __syncthreads();
    int o = threadIdx.x / 14, oh = threadIdx.x % 14;
    float acc[14];
#pragma unroll
    for (int p = 0; p < 14; p++) acc[p] = 0.f;
    for (int c = 0; c < 16; c++) {
#pragma unroll
        for (int kh = 0; kh < 3; kh++) {
            int ih = oh - 1 + kh;
            float r[16];
            r[0] = 0.f; r[15] = 0.f;
            if ((unsigned)ih < 14u) {
#pragma unroll
                for (int jj = 0; jj < 7; jj++) {  // c*196+ih*14 even -> aligned
                    float2 v2 = *reinterpret_cast<const float2*>(&xs[c * 196 + ih * 14 + 2 * jj]);
                    r[1 + 2 * jj] = v2.x;
                    r[2 + 2 * jj] = v2.y;
                }
            } else {
#pragma unroll
                for (int j = 0; j < 14; j++) r[j + 1] = 0.f;
            }
#pragma unroll
            for (int kw = 0; kw < 3; kw++) {
                float wv = ws[((o * 16 + c) * 3 + kh) * 3 + kw];
#pragma unroll
                for (int p = 0; p < 14; p++) acc[p] = fmaf(wv, r[p + kw], acc[p]);
            }
        }
    }
    float* vp = g_bufA + (size_t)t * 50176 + ((n * 32 + o) * 14 + oh) * 14;
#pragma unroll
    for (int p = 0; p < 14; p++) vp[p] = acc[p];
}

// K3: conv3 (32->64, 3x3, pad1, 7x7): D(psp4) -> C(v5).
// 224 threads = (o:32, oh:7), 2 channels/thread (o, o+32), scalar FFMA.
// x rows padded to stride 8 in smem -> float2 loads.
extern __shared__ float dynsm[];
__global__ void __launch_bounds__(224) k_conv3(const float* __restrict__ w) {
    float* ws = dynsm;            // 18432 floats
    float* xs = dynsm + 18432;    // 32*56 = 1792 floats (rows padded to 8)
    int b = blockIdx.x;
    int t = b >> 3;
    int n = b & 7;
    const float* xp = g_bufD + (size_t)t * 12544 + n * 1568;
    for (int i = threadIdx.x; i < 18432; i += 224) ws[i] = w[i];
    for (int i = threadIdx.x; i < 1568; i += 224) {
        int c = i / 49;
        int rr = i - c * 49;
        int ih = rr / 7;
        int j = rr - ih * 7;
        xs[c * 56 + ih * 8 + j] = xp[i];
    }
    __syncthreads();
    int o = threadIdx.x / 7, oh = threadIdx.x % 7;
    float acc0[7], acc1[7];
#pragma unroll
    for (int p = 0; p < 7; p++) { acc0[p] = 0.f; acc1[p] = 0.f; }
    for (int c = 0; c < 32; c++) {
#pragma unroll
        for (int kh = 0; kh < 3; kh++) {
            int ih = oh - 1 + kh;
            float r[9];
            r[0] = 0.f; r[8] = 0.f;
            if ((unsigned)ih < 7u) {
                int base = c * 56 + ih * 8;  // even -> 8B aligned
                float2 v0 = *reinterpret_cast<const float2*>(&xs[base]);
                float2 v1 = *reinterpret_cast<const float2*>(&xs[base + 2]);
                float2 v2 = *reinterpret_cast<const float2*>(&xs[base + 4]);
                r[1] = v0.x; r[2] = v0.y;
                r[3] = v1.x; r[4] = v1.y;
                r[5] = v2.x; r[6] = v2.y;
                r[7] = xs[base + 6];
            } else {
#pragma unroll
                for (int j = 1; j < 8; j++) r[j] = 0.f;
            }
#pragma unroll
            for (int kw = 0; kw < 3; kw++) {
                float w0 = ws[((o * 32 + c) * 3 + kh) * 3 + kw];
                float w1 = ws[(((o + 32) * 32 + c) * 3 + kh) * 3 + kw];
#pragma unroll
                for (int p = 0; p < 7; p++) {
                    acc0[p] = fmaf(w0, r[p + kw], acc0[p]);
                    acc1[p] = fmaf(w1, r[p + kw], acc1[p]);
                }
            }
        }
    }
    float* vp0 = g_bufC + (size_t)t * 25088 + ((n * 64 + o) * 7 + oh) * 7;
    float* vp1 = g_bufC + (size_t)t * 25088 + ((n * 64 + o + 32) * 7 + oh) * 7;
#pragma unroll
    for (int p = 0; p < 7; p++) { vp0[p] = acc0[p]; vp1[p] = acc1[p]; }
}

// K4: dense head, 4 timesteps per block (weight traffic /4): A -> Y.
__global__ void __launch_bounds__(256) k_fc(const float* __restrict__ w) {
    __shared__ float red[256];
    int b = blockIdx.x;
    int n = b & 7;
    int t0 = (b >> 3) * 4;
    const float* xp0 = g_bufA + (size_t)(t0 + 0) * 25088 + n * 3136;
    const float* xp1 = g_bufA + (size_t)(t0 + 1) * 25088 + n * 3136;
    const float* xp2 = g_bufA + (size_t)(t0 + 2) * 25088 + n * 3136;
    const float* xp3 = g_bufA + (size_t)(t0 + 3) * 25088 + n * 3136;
    float acc[40];
#pragma unroll
    for (int i = 0; i < 40; i++) acc[i] = 0.f;
    for (int j = threadIdx.x; j < 3136; j += 256) {
        float x0 = xp0[j], x1 = xp1[j], x2 = xp2[j], x3 = xp3[j];
#pragma unroll
        for (int o = 0; o < 10; o++) {
            float wv = w[o * 3136 + j];
            acc[0 * 10 + o] = fmaf(x0, wv, acc[0 * 10 + o]);
            acc[1 * 10 + o] = fmaf(x1, wv, acc[1 * 10 + o]);
            acc[2 * 10 + o] = fmaf(x2, wv, acc[2 * 10 + o]);
            acc[3 * 10 + o] = fmaf(x3, wv, acc[3 * 10 + o]);
        }
    }
    for (int tt = 0; tt < 4; tt++) {
#pragma unroll
        for (int o = 0; o < 10; o++) {
            red[threadIdx.x] = acc[tt * 10 + o];
            __syncthreads();
            for (int st = 128; st > 0; st >>= 1) {
                if (threadIdx.x < st) red[threadIdx.x] += red[threadIdx.x + st];
                __syncthreads();
            }
            if (threadIdx.x == 0)
                g_bufY[(size_t)(t0 + tt) * 80 + n * 10 + o] = red[0];
            __syncthreads();
        }
    }
}

// K5: final spike scan over 80 output neurons -> [8,10,300]
__global__ void k_spike_out(float* __restrict__ out) {
    int i = threadIdx.x;
    if (i >= 80) return;
    float ps = 0.f, qs = 0.f;
    for (int t = 0; t < TT; t++) {
        out[i * 300 + t] = spike_step(g_bufY[t * 80 + i], ps, qs);
    }
}

extern "C" void kernel_launch(void* const* d_in, const int* in_sizes, int n_in,
                              void* d_out, int out_size) {
    const float* x  = (const float*)d_in[0];   // [8,1,30,30,300]
    const float* w1 = (const float*)d_in[1];   // [16,1,5,5]
    const float* w2 = (const float*)d_in[2];   // [32,16,3,3]
    const float* w3 = (const float*)d_in[3];   // [64,32,3,3]
    const float* wf = (const float*)d_in[4];   // [10,64,7,7]
    float* out = (float*)d_out;

    float *bufA, *bufC, *bufD;
    cudaGetSymbolAddress((void**)&bufA, g_bufA);
    cudaGetSymbolAddress((void**)&bufC, g_bufC);
    cudaGetSymbolAddress((void**)&bufD, g_bufD);

    // conv3: (18432 + 1792) * 4 = 80896 bytes dynamic smem
    cudaFuncSetAttribute(k_conv3, cudaFuncAttributeMaxDynamicSharedMemorySize, 80896);

    k_psp0<<<(7200 + 127) / 128, 128>>>(x);                          // x -> D (psp0)
    k_conv1<<<2400, 448>>>(w1);                                      // D -> A (v1)
    k_fused_pool<<<(25088 + 127) / 128, 128>>>(bufA, bufC,
                                   16, 14, 14, 100352, 25088);       // A -> C (psp2)
    k_conv2<<<2400, 448>>>(w2);                                      // C -> A (v3)
    k_fused_pool<<<(12544 + 63) / 64, 64>>>(bufA, bufD,
                                   32, 7, 7, 50176, 12544);          // A -> D (psp4)
    k_conv3<<<2400, 224, 80896>>>(w3);                               // D -> C (v5)
    k_spike_psp<<<(25088 + 127) / 128, 128>>>(bufC, bufA, 25088);    // C -> A (psp5)
    k_fc<<<600, 256>>>(wf);                                          // A -> Y
    k_spike_out<<<1, 128>>>(out);                                    // Y -> out
}

// round 8
// speedup vs baseline: 1.4820x; 1.0216x over previous
#include <cuda_runtime.h>

#define TT 300
// SLAYER constants
#define D_SR 0.9048374180359595f    // exp(-Ts/tauSr), tauSr=10
#define B_SR 0.2718281828459045f    // e*Ts/tauSr
#define D_RF 0.3678794411714423f    // exp(-Ts/tauRef), tauRef=1
#define A_RF -54.365636569180902f   // -scaleRef*theta*e*Ts/tauRef
#define THETA 10.0f
#define PGAIN 11.0f                 // 1.1*theta

// ---- scratch arenas (time-major [t][n][c][h][w]) ----
// A: v1[300x100352] / v3[300x50176] / psp5[300x25088]
// C: psp2[300x25088]  / v5[300x25088]
// D: psp0[300x7200] / psp4[300x12544]
__device__ float g_bufA[30105600];
__device__ float g_bufC[7526400];
__device__ float g_bufD[3763200];
__device__ float g_bufY[24000];

// --- exact-order recurrence steps (no fma contraction, matching XLA) ---
__device__ __forceinline__ float psp_step(float x, float& p, float& q) {
    q = __fmul_rn(D_SR, __fadd_rn(q, p));
    float out = __fmul_rn(B_SR, q);
    p = __fadd_rn(__fmul_rn(D_SR, p), x);
    return out;
}
__device__ __forceinline__ float spike_step(float u, float& p, float& q) {
    q = __fmul_rn(D_RF, __fadd_rn(q, p));
    float m = __fadd_rn(u, __fmul_rn(A_RF, q));
    float s = (m >= THETA) ? 1.0f : 0.0f;
    p = __fadd_rn(__fmul_rn(D_RF, p), s);
    return s;
}

// K0: psp of raw input. in [j=7200][t] -> time-major psp0 in bufD.
__global__ void k_psp0(const float* __restrict__ in) {
    int j = blockIdx.x * blockDim.x + threadIdx.x;
    if (j >= 7200) return;
    const float4* xp = reinterpret_cast<const float4*>(in + (size_t)j * TT);
    float p = 0.f, q = 0.f;
    float4 cur = xp[0];
    for (int tb = 0; tb < 75; tb++) {
        float4 nxt;
        if (tb < 74) nxt = xp[tb + 1];
        g_bufD[(size_t)(4 * tb + 0) * 7200 + j] = psp_step(cur.x, p, q);
        g_bufD[(size_t)(4 * tb + 1) * 7200 + j] = psp_step(cur.y, p, q);
        g_bufD[(size_t)(4 * tb + 2) * 7200 + j] = psp_step(cur.z, p, q);
        g_bufD[(size_t)(4 * tb + 3) * 7200 + j] = psp_step(cur.w, p, q);
        cur = nxt;
    }
}

// Fused: 4 parent drives -> [spike->psp]x4 -> pool*gain -> spike -> psp.
__global__ void k_fused_pool(const float* __restrict__ v, float* __restrict__ po,
                             int C, int Ho, int Wo, int nn_in, int nn_out) {
    int i = blockIdx.x * blockDim.x + threadIdx.x;
    if (i >= nn_out) return;
    int per = C * Ho * Wo;
    int n = i / per;
    int rem = i - n * per;
    int c = rem / (Ho * Wo);
    int r2 = rem - c * (Ho * Wo);
    int oh = r2 / Wo, ow = r2 - oh * Wo;
    int Wi = 2 * Wo;
    size_t base = ((size_t)(n * C + c) * (2 * Ho) + 2 * oh) * Wi + 2 * ow;

    float ps[4], qs[4], pp[4], qq[4];
#pragma unroll
    for (int jj = 0; jj < 4; jj++) { ps[jj] = 0.f; qs[jj] = 0.f; pp[jj] = 0.f; qq[jj] = 0.f; }
    float psO = 0.f, qsO = 0.f, ppO = 0.f, qqO = 0.f;

    const int CH = 10;
    float cur[4 * CH], nxt[4 * CH];
#pragma unroll
    for (int k = 0; k < CH; k++) {
        const float* bp = v + (size_t)k * nn_in + base;
        cur[4 * k + 0] = bp[0];
        cur[4 * k + 1] = bp[1];
        cur[4 * k + 2] = bp[Wi];
        cur[4 * k + 3] = bp[Wi + 1];
    }
    for (int tb = 0; tb < TT / CH; tb++) {
        if (tb + 1 < TT / CH) {
#pragma unroll
            for (int k = 0; k < CH; k++) {
                const float* bp = v + (size_t)((tb + 1) * CH + k) * nn_in + base;
                nxt[4 * k + 0] = bp[0];
                nxt[4 * k + 1] = bp[1];
                nxt[4 * k + 2] = bp[Wi];
                nxt[4 * k + 3] = bp[Wi + 1];
            }
        }
#pragma unroll
        for (int k = 0; k < CH; k++) {
            float pv[4];
#pragma unroll
            for (int jj = 0; jj < 4; jj++) {
                float s = spike_step(cur[4 * k + jj], ps[jj], qs[jj]);
                pv[jj] = psp_step(s, pp[jj], qq[jj]);
            }
            float u = __fmul_rn(PGAIN,
                __fadd_rn(__fadd_rn(pv[0], pv[1]), __fadd_rn(pv[2], pv[3])));
            float s2 = spike_step(u, psO, qsO);
            po[(size_t)(tb * CH + k) * nn_out + i] = psp_step(s2, ppO, qqO);
        }
#pragma unroll
        for (int k = 0; k < 4 * CH; k++) cur[k] = nxt[k];
    }
}

// Fused spike(v) -> psp(s), chunked double-buffer prefetch.
__global__ void k_spike_psp(const float* __restrict__ v, float* __restrict__ po, int nn) {
    int i = blockIdx.x * blockDim.x + threadIdx.x;
    if (i >= nn) return;
    float ps = 0.f, qs = 0.f, pp = 0.f, qq = 0.f;
    const int CH = 10;
    float cur[CH], nxt[CH];
#pragma unroll
    for (int k = 0; k < CH; k++) cur[k] = v[(size_t)k * nn + i];
    for (int tb = 0; tb < TT / CH; tb++) {
        if (tb + 1 < TT / CH) {
#pragma unroll
            for (int k = 0; k < CH; k++)
                nxt[k] = v[(size_t)((tb + 1) * CH + k) * nn + i];
        }
#pragma unroll
        for (int k = 0; k < CH; k++) {
            float s = spike_step(cur[k], ps, qs);
            po[(size_t)(tb * CH + k) * nn + i] = psp_step(s, pp, qq);
        }
#pragma unroll
        for (int k = 0; k < CH; k++) cur[k] = nxt[k];
    }
}

// K1: conv1 (1->16, 5x5, pad1, 30->28). D -> A. 448 thr, float2 row loads.
__global__ void __launch_bounds__(448) k_conv1(const float* __restrict__ w) {
    __shared__ __align__(16) float xs[900];
    __shared__ float ws[400];
    int b = blockIdx.x;
    int t = b >> 3;
    int n = b & 7;
    const float* xp = g_bufD + (size_t)t * 7200 + n * 900;
    for (int i = threadIdx.x; i < 900; i += 448) xs[i] = xp[i];
    for (int i = threadIdx.x; i < 400; i += 448) ws[i] = w[i];
    __syncthreads();
    int o = threadIdx.x / 28;
    int oh = threadIdx.x % 28;
    float acc[28];
#pragma unroll
    for (int p = 0; p < 28; p++) acc[p] = 0.f;
#pragma unroll
    for (int kh = 0; kh < 5; kh++) {
        int ih = oh - 1 + kh;
        if ((unsigned)ih < 30u) {
            float r[32];
            r[0] = 0.f; r[31] = 0.f;
#pragma unroll
            for (int jj = 0; jj < 15; jj++) {  // ih*30 even -> 8B aligned
                float2 v2 = *reinterpret_cast<const float2*>(&xs[ih * 30 + 2 * jj]);
                r[1 + 2 * jj] = v2.x;
                r[2 + 2 * jj] = v2.y;
            }
#pragma unroll
            for (int kw = 0; kw < 5; kw++) {
                float wv = ws[o * 25 + kh * 5 + kw];
#pragma unroll
                for (int p = 0; p < 28; p++) acc[p] = fmaf(wv, r[p + kw], acc[p]);
            }
        }
    }
    float* vp = g_bufA + (size_t)t * 100352 + ((n * 16 + o) * 28 + oh) * 28;
#pragma unroll
    for (int p = 0; p < 28; p++) vp[p] = acc[p];
}

// K2: conv2 (16->32, 3x3, pad1, 14x14): C(psp2) -> A(v3).
// 224 threads = (o:16, oh:14); each thread computes channels o and o+16
// with SCALAR FFMA (no packing). Each x-row load feeds 84 FMAs -> crossbar
// traffic per FMA halved vs 1-channel version. Per-output order unchanged.
__global__ void __launch_bounds__(224) k_conv2(const float* __restrict__ w) {
    __shared__ __align__(16) float xs[3136];   // 16*14*14
    __shared__ float ws[4608];                 // 32*16*9
    int b = blockIdx.x;
    int t = b >> 3;
    int n = b & 7;
    const float* xp = g_bufC + (size_t)t * 25088 + n * 3136;
    for (int i = threadIdx.x; i < 3136; i += 224) xs[i] = xp[i];
    for (int i = threadIdx.x; i < 4608; i += 224) ws[i] = w[i];
    __syncthreads();
    int o = threadIdx.x / 14, oh = threadIdx.x % 14;
    float acc0[14], acc1[14];
#pragma unroll
    for (int p = 0; p < 14; p++) { acc0[p] = 0.f; acc1[p] = 0.f; }
    for (int c = 0; c < 16; c++) {
#pragma unroll
        for (int kh = 0; kh < 3; kh++) {
            int ih = oh - 1 + kh;
            float r[16];
            r[0] = 0.f; r[15] = 0.f;
            if ((unsigned)ih < 14u) {
#pragma unroll
                for (int jj = 0; jj < 7; jj++) {  // c*196+ih*14 even -> aligned
                    float2 v2 = *reinterpret_cast<const float2*>(&xs[c * 196 + ih * 14 + 2 * jj]);
                    r[1 + 2 * jj] = v2.x;
                    r[2 + 2 * jj] = v2.y;
                }
            } else {
#pragma unroll
                for (int j = 0; j < 14; j++) r[j + 1] = 0.f;
            }
#pragma unroll
            for (int kw = 0; kw < 3; kw++) {
                float w0 = ws[((o * 16 + c) * 3 + kh) * 3 + kw];
                float w1 = ws[(((o + 16) * 16 + c) * 3 + kh) * 3 + kw];
#pragma unroll
                for (int p = 0; p < 14; p++) {
                    acc0[p] = fmaf(w0, r[p + kw], acc0[p]);
                    acc1[p] = fmaf(w1, r[p + kw], acc1[p]);
                }
            }
        }
    }
    float* vp0 = g_bufA + (size_t)t * 50176 + ((n * 32 + o) * 14 + oh) * 14;
    float* vp1 = g_bufA + (size_t)t * 50176 + ((n * 32 + o + 16) * 14 + oh) * 14;
#pragma unroll
    for (int p = 0; p < 14; p++) { vp0[p] = acc0[p]; vp1[p] = acc1[p]; }
}

// K3: conv3 (32->64, 3x3, pad1, 7x7): D(psp4) -> C(v5).
// 448 threads = 2 (t,n) units x (o:32, oh:7); 2 channels/thread (o, o+32),
// scalar FFMA, x rows padded to stride 8 -> float2 loads. Weights loaded
// once per block for both units (L2 weight traffic halved vs 1-unit).
extern __shared__ float dynsm[];
__global__ void __launch_bounds__(448) k_conv3(const float* __restrict__ w) {
    float* ws = dynsm;            // 18432 floats
    float* xs = dynsm + 18432;    // 2 * 1792 floats (rows padded to 8)
    int b = blockIdx.x;
    int u0 = 2 * b;
    for (int i = threadIdx.x; i < 18432; i += 448) ws[i] = w[i];
    for (int i = threadIdx.x; i < 3136; i += 448) {
        int g2 = i / 1568;
        int rem = i - g2 * 1568;
        int c = rem / 49;
        int rr = rem - c * 49;
        int ih = rr / 7;
        int j = rr - ih * 7;
        int u = u0 + g2;
        const float* xp = g_bufD + (size_t)(u >> 3) * 12544 + (u & 7) * 1568;
        xs[g2 * 1792 + c * 56 + ih * 8 + j] = xp[rem];
    }
    __syncthreads();
    int g = threadIdx.x / 224;
    int idx = threadIdx.x - g * 224;
    int o = idx / 7, oh = idx % 7;
    const float* X = xs + g * 1792;
    int u = u0 + g;
    int t = u >> 3, n = u & 7;
    float acc0[7], acc1[7];
#pragma unroll
    for (int p = 0; p < 7; p++) { acc0[p] = 0.f; acc1[p] = 0.f; }
    for (int c = 0; c < 32; c++) {
#pragma unroll
        for (int kh = 0; kh < 3; kh++) {
            int ih = oh - 1 + kh;
            float r[9];
            r[0] = 0.f; r[8] = 0.f;
            if ((unsigned)ih < 7u) {
                int base = c * 56 + ih * 8;  // even -> 8B aligned
                float2 v0 = *reinterpret_cast<const float2*>(&X[base]);
                float2 v1 = *reinterpret_cast<const float2*>(&X[base + 2]);
                float2 v2 = *reinterpret_cast<const float2*>(&X[base + 4]);
                r[1] = v0.x; r[2] = v0.y;
                r[3] = v1.x; r[4] = v1.y;
                r[5] = v2.x; r[6] = v2.y;
                r[7] = X[base + 6];
            } else {
#pragma unroll
                for (int j = 1; j < 8; j++) r[j] = 0.f;
            }
#pragma unroll
            for (int kw = 0; kw < 3; kw++) {
                float w0 = ws[((o * 32 + c) * 3 + kh) * 3 + kw];
                float w1 = ws[(((o + 32) * 32 + c) * 3 + kh) * 3 + kw];
#pragma unroll
                for (int p = 0; p < 7; p++) {
                    acc0[p] = fmaf(w0, r[p + kw], acc0[p]);
                    acc1[p] = fmaf(w1, r[p + kw], acc1[p]);
                }
            }
        }
    }
    float* vp0 = g_bufC + (size_t)t * 25088 + ((n * 64 + o) * 7 + oh) * 7;
    float* vp1 = g_bufC + (size_t)t * 25088 + ((n * 64 + o + 32) * 7 + oh) * 7;
#pragma unroll
    for (int p = 0; p < 7; p++) { vp0[p] = acc0[p]; vp1[p] = acc1[p]; }
}

// K4: dense head per timestep on psp5 floats: A -> Y[t][n][o]. (R3 version)
__global__ void __launch_bounds__(256) k_fc(const float* __restrict__ w) {
    __shared__ float red[256];
    int b = blockIdx.x;
    int t = b >> 3;
    int n = b & 7;
    const float* xp = g_bufA + (size_t)t * 25088 + n * 3136;
    float acc[10];
#pragma unroll
    for (int o = 0; o < 10; o++) acc[o] = 0.f;
    for (int j = threadIdx.x; j < 3136; j += 256) {
        float xv = xp[j];
#pragma unroll
        for (int o = 0; o < 10; o++) acc[o] = fmaf(xv, w[o * 3136 + j], acc[o]);
    }
#pragma unroll
    for (int o = 0; o < 10; o++) {
        red[threadIdx.x] = acc[o];
        __syncthreads();
        for (int st = 128; st > 0; st >>= 1) {
            if (threadIdx.x < st) red[threadIdx.x] += red[threadIdx.x + st];
            __syncthreads();
        }
        if (threadIdx.x == 0) g_bufY[(size_t)t * 80 + n * 10 + o] = red[0];
        __syncthreads();
    }
}

// K5: final spike scan over 80 output neurons -> [8,10,300]
__global__ void k_spike_out(float* __restrict__ out) {
    int i = threadIdx.x;
    if (i >= 80) return;
    float ps = 0.f, qs = 0.f;
    for (int t = 0; t < TT; t++) {
        out[i * 300 + t] = spike_step(g_bufY[t * 80 + i], ps, qs);
    }
}

extern "C" void kernel_launch(void* const* d_in, const int* in_sizes, int n_in,
                              void* d_out, int out_size) {
    const float* x  = (const float*)d_in[0];   // [8,1,30,30,300]
    const float* w1 = (const float*)d_in[1];   // [16,1,5,5]
    const float* w2 = (const float*)d_in[2];   // [32,16,3,3]
    const float* w3 = (const float*)d_in[3];   // [64,32,3,3]
    const float* wf = (const float*)d_in[4];   // [10,64,7,7]
    float* out = (float*)d_out;

    float *bufA, *bufC, *bufD;
    cudaGetSymbolAddress((void**)&bufA, g_bufA);
    cudaGetSymbolAddress((void**)&bufC, g_bufC);
    cudaGetSymbolAddress((void**)&bufD, g_bufD);

    // conv3: (18432 + 2*1792) * 4 = 88064 bytes dynamic smem
    cudaFuncSetAttribute(k_conv3, cudaFuncAttributeMaxDynamicSharedMemorySize, 88064);

    k_psp0<<<(7200 + 127) / 128, 128>>>(x);                          // x -> D (psp0)
    k_conv1<<<2400, 448>>>(w1);                                      // D -> A (v1)
    k_fused_pool<<<(25088 + 127) / 128, 128>>>(bufA, bufC,
                                   16, 14, 14, 100352, 25088);       // A -> C (psp2)
    k_conv2<<<2400, 224>>>(w2);                                      // C -> A (v3)
    k_fused_pool<<<(12544 + 63) / 64, 64>>>(bufA, bufD,
                                   32, 7, 7, 50176, 12544);          // A -> D (psp4)
    k_conv3<<<1200, 448, 88064>>>(w3);                               // D -> C (v5)
    k_spike_psp<<<(25088 + 127) / 128, 128>>>(bufC, bufA, 25088);    // C -> A (psp5)
    k_fc<<<2400, 256>>>(wf);                                         // A -> Y
    k_spike_out<<<1, 128>>>(out);                                    // Y -> out
}